// round 16
// baseline (speedup 1.0000x reference)
#include <cuda_runtime.h>
#include <cuda_bf16.h>

#define B_    32
#define H_    64
#define KVH_  8
#define D_    128
#define HID_  8192
#define CL_   1024
#define SP_   511
#define NTOT  10240

// ---------------- scratch ----------------
__device__ float    g_qkv[B_ * NTOT];       // fp32 qkv [b][n] (split-K accumulated)
__device__ unsigned g_xhi[B_ * 4096];       // x hi bf16x2 [b][k/2]
__device__ unsigned g_xlo[B_ * 4096];
__device__ unsigned g_ahi[B_ * 4096];       // attn out hi bf16x2 [b][k/2]
__device__ unsigned g_alo[B_ * 4096];
__device__ float    g_part[2048 * 8 * 132]; // attn partials [(b,kv,split)][head][128 acc + m + s]

// gemm smem (48 KB): WHI[2]x8K, WLO[2]x8K, BHI[2]x4K, BLO[2]x4K
#define SMW_HI(buf) ((buf) * 8192)
#define SMW_LO(buf) (16384 + (buf) * 8192)
#define SMB_HI(buf) (32768 + (buf) * 4096)
#define SMB_LO(buf) (40960 + (buf) * 4096)
#define SM_TOT 49152

// ---------------- helpers ----------------
// truncation-based hi/lo split, PRMT-packed (6 instr).
__device__ __forceinline__ void split2(float f0, float f1, unsigned& hi, unsigned& lo) {
    unsigned u0 = __float_as_uint(f0), u1 = __float_as_uint(f1);
    unsigned h;
    asm("prmt.b32 %0, %1, %2, 0x7632;" : "=r"(h) : "r"(u0), "r"(u1));
    float l0 = f0 - __uint_as_float(u0 & 0xffff0000u);
    float l1 = f1 - __uint_as_float(u1 & 0xffff0000u);
    unsigned v0 = __float_as_uint(l0), v1 = __float_as_uint(l1);
    unsigned l;
    asm("prmt.b32 %0, %1, %2, 0x7632;" : "=r"(l) : "r"(v0), "r"(v1));
    hi = h;
    lo = l;
}

__device__ __forceinline__ void ldsm4(unsigned& r0, unsigned& r1, unsigned& r2,
                                      unsigned& r3, unsigned addr) {
    asm volatile("ldmatrix.sync.aligned.m8n8.x4.shared.b16 {%0,%1,%2,%3}, [%4];"
                 : "=r"(r0), "=r"(r1), "=r"(r2), "=r"(r3) : "r"(addr));
}

__device__ __forceinline__ void mma16816(float* c, const unsigned* a,
                                         unsigned b0, unsigned b1) {
    asm volatile(
        "mma.sync.aligned.m16n8k16.row.col.f32.bf16.bf16.f32 "
        "{%0,%1,%2,%3}, {%4,%5,%6,%7}, {%8,%9}, {%0,%1,%2,%3};"
        : "+f"(c[0]), "+f"(c[1]), "+f"(c[2]), "+f"(c[3])
        : "r"(a[0]), "r"(a[1]), "r"(a[2]), "r"(a[3]), "r"(b0), "r"(b1));
}

// rope a float4 at dim base 4*l (pairs 2l, 2l+1)
__device__ __forceinline__ float4 rope4(float4 v, int l, const float* __restrict__ rm) {
    float c0 = rm[(4 * l)     * D_ + 4 * l];
    float s0 = rm[(4 * l + 1) * D_ + 4 * l];
    float c1 = rm[(4 * l + 2) * D_ + 4 * l + 2];
    float s1 = rm[(4 * l + 3) * D_ + 4 * l + 2];
    float4 r;
    r.x = fmaf(v.x, c0,  v.y * s0);
    r.y = fmaf(v.y, c0, -v.x * s0);
    r.z = fmaf(v.z, c1,  v.w * s1);
    r.w = fmaf(v.w, c1, -v.z * s1);
    return r;
}

// ---------------- fused zero + cvt ----------------
__global__ void prep_kernel(const float* __restrict__ x, float* __restrict__ out) {
    const int n1 = B_ * NTOT;
    const int n2 = B_ * HID_;
    const int n3 = B_ * HID_ / 2;
    int t = blockIdx.x * blockDim.x + threadIdx.x;
    if (t < n1) {
        g_qkv[t] = 0.0f;
    } else if (t < n1 + n2) {
        out[t - n1] = 0.0f;
    } else if (t < n1 + n2 + n3) {
        int i = t - n1 - n2;
        float f0 = x[2 * i], f1 = x[2 * i + 1];
        unsigned h, l;
        split2(f0, f1, h, l);
        g_xhi[i] = h;
        g_xlo[i] = l;
    }
}

// ---------------- HMMA GEMM: Kchunk=64, split-K=4, lookahead-2, occ 3 -------
__global__ __launch_bounds__(256, 3)
void gemm_mma(int bsel,
              const float* __restrict__ W0, const float* __restrict__ W1,
              const float* __restrict__ W2,
              int nb1, int nb2,
              int csel, float* __restrict__ Cext, int ldc)
{
    extern __shared__ char smem[];
    unsigned sb = (unsigned)__cvta_generic_to_shared(smem);
    int tid = threadIdx.x, lane = tid & 31, wid = tid >> 5;

    int n0 = blockIdx.x * 64;
    const float* W; int wrow;
    if (n0 < nb1)      { W = W0; wrow = n0; }
    else if (n0 < nb2) { W = W1; wrow = n0 - nb1; }
    else               { W = W2; wrow = n0 - nb2; }

    const unsigned* __restrict__ Bh = bsel ? g_ahi : g_xhi;
    const unsigned* __restrict__ Bl = bsel ? g_alo : g_xlo;
    float* C = csel ? Cext : g_qkv;

    int kbase = blockIdx.y * (HID_ / 4);                // split-K=4
    const float* wbase = W + (size_t)wrow * HID_ + kbase;
    int kw0 = kbase >> 1;

    int rg   = wid >> 1;
    int bh16 = wid & 1;

    int arow = rg * 16 + (lane & 7) + ((lane >> 3) & 1) * 8;
    int acs  = (lane >> 4) & 1;
    int arm  = arow & 7;
    int brow = bh16 * 16 + (lane & 7) + ((lane >> 4) & 1) * 8;
    int bcs  = (lane >> 3) & 1;
    int brm  = brow & 7;

    float4 wregA[4], wregB[4];
    uint4  bhA, blA, bhB, blB;

    float acc[2][4];
    #pragma unroll
    for (int i = 0; i < 2; ++i)
        #pragma unroll
        for (int j = 0; j < 4; ++j) acc[i][j] = 0.0f;

    #define LOADC(c, WR, BHR, BLR) do {                                          \
        _Pragma("unroll")                                                        \
        for (int i_ = 0; i_ < 4; ++i_) {                                         \
            int idx_ = tid + 256 * i_;                                           \
            int row_ = idx_ >> 4, kq_ = idx_ & 15;                               \
            WR[i_] = __ldcs((const float4*)(wbase + (c) * 64                     \
                            + (size_t)row_ * HID_ + kq_ * 4));                   \
        }                                                                        \
        {                                                                        \
            int n_ = tid >> 3, s_ = tid & 7;                                     \
            size_t off_ = (size_t)n_ * 4096 + kw0 + (c) * 32 + s_ * 4;           \
            BHR = *(const uint4*)(Bh + off_);                                    \
            BLR = *(const uint4*)(Bl + off_);                                    \
        }                                                                        \
    } while (0)

    #define STOREC(buf, WR, BHR, BLR) do {                                       \
        _Pragma("unroll")                                                        \
        for (int i_ = 0; i_ < 4; ++i_) {                                         \
            int idx_ = tid + 256 * i_;                                           \
            int row_ = idx_ >> 4, kq_ = idx_ & 15;                               \
            unsigned h0_, l0_, h1_, l1_;                                         \
            split2(WR[i_].x, WR[i_].y, h0_, l0_);                                \
            split2(WR[i_].z, WR[i_].w, h1_, l1_);                                \
            unsigned off_ = (unsigned)(row_ * 128)                               \
                          + ((((unsigned)kq_ >> 1) ^ (unsigned)(row_ & 7)) << 4) \
                          + (((unsigned)kq_ & 1u) << 3);                         \
            *(uint2*)(smem + SMW_HI(buf) + off_) = make_uint2(h0_, h1_);         \
            *(uint2*)(smem + SMW_LO(buf) + off_) = make_uint2(l0_, l1_);         \
        }                                                                        \
        {                                                                        \
            int n_ = tid >> 3, s_ = tid & 7;                                     \
            unsigned off_ = (unsigned)(n_ * 128)                                 \
                          + (((unsigned)s_ ^ (unsigned)(n_ & 7)) << 4);          \
            *(uint4*)(smem + SMB_HI(buf) + off_) = BHR;                          \
            *(uint4*)(smem + SMB_LO(buf) + off_) = BLR;                          \
        }                                                                        \
    } while (0)

    #define COMPUTE(buf) do {                                                    \
        unsigned wh0 = sb + SMW_HI(buf), wl0 = sb + SMW_LO(buf);                 \
        unsigned bb0 = sb + SMB_HI(buf), bl0 = sb + SMB_LO(buf);                 \
        _Pragma("unroll")                                                        \
        for (int s = 0; s < 4; ++s) {                                            \
            unsigned aoff = (unsigned)(arow * 128)                               \
                          + (((unsigned)(2 * s + acs) ^ (unsigned)arm) << 4);    \
            unsigned ah[4], al[4];                                               \
            ldsm4(ah[0], ah[1], ah[2], ah[3], wh0 + aoff);                       \
            ldsm4(al[0], al[1], al[2], al[3], wl0 + aoff);                       \
            unsigned boff = (unsigned)(brow * 128)                               \
                          + (((unsigned)(2 * s + bcs) ^ (unsigned)brm) << 4);    \
            unsigned bh[4], bl[4];                                               \
            ldsm4(bh[0], bh[1], bh[2], bh[3], bb0 + boff);                       \
            ldsm4(bl[0], bl[1], bl[2], bl[3], bl0 + boff);                       \
            mma16816(acc[0], ah, bh[0], bh[1]);                                  \
            mma16816(acc[1], ah, bh[2], bh[3]);                                  \
            mma16816(acc[0], al, bh[0], bh[1]);                                  \
            mma16816(acc[1], al, bh[2], bh[3]);                                  \
            mma16816(acc[0], ah, bl[0], bl[1]);                                  \
            mma16816(acc[1], ah, bl[2], bl[3]);                                  \
        }                                                                        \
    } while (0)

    const int NCH = (HID_ / 4) / 64;    // 32 chunks (even)

    // prologue: load chunks 0 (A) and 1 (B); stage chunk 0
    LOADC(0, wregA, bhA, blA);
    LOADC(1, wregB, bhB, blB);
    STOREC(0, wregA, bhA, blA);
    __syncthreads();

    for (int c = 0; c < NCH; c += 2) {
        // even chunk c (buf0); A regs become free -> prefetch c+2
        if (c + 2 < NCH) LOADC(c + 2, wregA, bhA, blA);
        COMPUTE(0);
        STOREC(1, wregB, bhB, blB);              // chunk c+1, loaded 1 iter ago
        __syncthreads();

        // odd chunk c+1 (buf1); B regs free -> prefetch c+3
        if (c + 3 < NCH) LOADC(c + 3, wregB, bhB, blB);
        COMPUTE(1);
        if (c + 2 < NCH) STOREC(0, wregA, bhA, blA);   // chunk c+2
        __syncthreads();
    }

    int g = lane >> 2, t4 = lane & 3;
    int m = n0 + rg * 16 + g;
    #pragma unroll
    for (int nt = 0; nt < 2; ++nt) {
        int col = bh16 * 16 + nt * 8 + 2 * t4;
        atomicAdd(&C[(size_t)col * ldc + m],           acc[nt][0]);
        atomicAdd(&C[(size_t)(col + 1) * ldc + m],     acc[nt][1]);
        atomicAdd(&C[(size_t)col * ldc + m + 8],       acc[nt][2]);
        atomicAdd(&C[(size_t)(col + 1) * ldc + m + 8], acc[nt][3]);
    }
    #undef LOADC
    #undef STOREC
    #undef COMPUTE
}

// ---------------- attention split v4 (R14 winner, unchanged) ----------------
__global__ __launch_bounds__(256)
void attn_split(const float* __restrict__ cache_k,
                const float* __restrict__ cache_v,
                const float* __restrict__ rm)
{
    __shared__ float sQ[8][128];
    __shared__ float sK[64 * 128];
    __shared__ float sS[64 * 9];

    int bidx  = blockIdx.x;
    int split = bidx & 7;
    int bk    = bidx >> 3;
    int b  = bk >> 3;
    int kv = bk & 7;
    int p0 = split * 64;

    int tid  = threadIdx.x;
    int w    = tid >> 5;
    int lane = tid & 31;

    const float scale = 0.0883883476483184405501055452631f;

    const float* kb   = cache_k + ((size_t)(b * KVH_ + kv)) * CL_ * D_;
    const float* vb   = cache_v + ((size_t)(b * KVH_ + kv)) * CL_ * D_;
    const float* knew = g_qkv + (size_t)b * NTOT + HID_ + kv * D_;
    const float* vnew = g_qkv + (size_t)b * NTOT + HID_ + KVH_ * D_ + kv * D_;

    {
        float4 q = *(const float4*)(g_qkv + (size_t)b * NTOT + (kv * 8 + w) * D_ + lane * 4);
        q = rope4(q, lane, rm);
        q.x *= scale; q.y *= scale; q.z *= scale; q.w *= scale;
        *(float4*)&sQ[w][lane * 4] = q;
    }
    #pragma unroll
    for (int i = 0; i < 8; ++i) {
        int v = tid + 256 * i;
        int j = v >> 5, dq = v & 31;
        int s = p0 + j;
        float4 kd;
        if (s == SP_) kd = rope4(*(const float4*)(knew + dq * 4), dq, rm);
        else          kd = __ldcs((const float4*)(kb + (size_t)s * D_ + dq * 4));
        *(float4*)&sK[j * 128 + dq * 4] = kd;
    }
    __syncthreads();

    float4 qreg[8];
    #pragma unroll
    for (int h = 0; h < 8; ++h)
        qreg[h] = *(const float4*)&sQ[h][lane * 4];

    #pragma unroll
    for (int p = 0; p < 8; ++p) {
        int j = w * 8 + p;
        float4 v4 = *(const float4*)&sK[j * 128 + lane * 4];
        float pr[8];
        #pragma unroll
        for (int h = 0; h < 8; ++h)
            pr[h] = fmaf(qreg[h].x, v4.x, fmaf(qreg[h].y, v4.y,
                    fmaf(qreg[h].z, v4.z, qreg[h].w * v4.w)));
        #pragma unroll
        for (int h = 0; h < 8; ++h) {
            pr[h] += __shfl_xor_sync(0xffffffffu, pr[h], 16);
            pr[h] += __shfl_xor_sync(0xffffffffu, pr[h], 8);
        }
        float s4[4];
        #pragma unroll
        for (int i = 0; i < 4; ++i) {
            float r1 = __shfl_xor_sync(0xffffffffu, pr[i], 4);
            float r2 = __shfl_xor_sync(0xffffffffu, pr[i + 4], 4);
            s4[i] = (lane & 4) ? (pr[i + 4] + r2) : (pr[i] + r1);
        }
        float s2[2];
        #pragma unroll
        for (int i = 0; i < 2; ++i) {
            float r1 = __shfl_xor_sync(0xffffffffu, s4[i], 2);
            float r2 = __shfl_xor_sync(0xffffffffu, s4[i + 2], 2);
            s2[i] = (lane & 2) ? (s4[i + 2] + r2) : (s4[i] + r1);
        }
        float r1 = __shfl_xor_sync(0xffffffffu, s2[0], 1);
        float r2 = __shfl_xor_sync(0xffffffffu, s2[1], 1);
        float f  = (lane & 1) ? (s2[1] + r2) : (s2[0] + r1);
        if (lane < 8) sS[j * 9 + lane] = f;
    }
    __syncthreads();

    {
        float v1 = sS[lane * 9 + w];
        float v2 = sS[(lane + 32) * 9 + w];
        float mx = fmaxf(v1, v2);
        #pragma unroll
        for (int o = 16; o; o >>= 1) mx = fmaxf(mx, __shfl_xor_sync(0xffffffffu, mx, o));
        float e1 = __expf(v1 - mx), e2 = __expf(v2 - mx);
        float sum = e1 + e2;
        #pragma unroll
        for (int o = 16; o; o >>= 1) sum += __shfl_xor_sync(0xffffffffu, sum, o);
        sS[lane * 9 + w]        = e1;
        sS[(lane + 32) * 9 + w] = e2;
        if (lane == 0) {
            float* pp = g_part + ((size_t)bidx * 8 + w) * 132;
            pp[128] = mx;
            pp[129] = sum;
        }
    }
    #pragma unroll
    for (int i = 0; i < 8; ++i) {
        int v = tid + 256 * i;
        int j = v >> 5, dq = v & 31;
        int s = p0 + j;
        float4 vd = (s == SP_) ? *(const float4*)(vnew + dq * 4)
                               : __ldcs((const float4*)(vb + (size_t)s * D_ + dq * 4));
        *(float4*)&sK[j * 128 + dq * 4] = vd;
    }
    __syncthreads();

    float pA = sS[(w * 8 +     (lane >> 3)) * 9 + (lane & 7)];
    float pB = sS[(w * 8 + 4 + (lane >> 3)) * 9 + (lane & 7)];
    float4 acc[8];
    #pragma unroll
    for (int h = 0; h < 8; ++h) acc[h] = make_float4(0.f, 0.f, 0.f, 0.f);
    #pragma unroll
    for (int p = 0; p < 8; ++p) {
        int j = w * 8 + p;
        float4 v4 = *(const float4*)&sK[j * 128 + lane * 4];
        #pragma unroll
        for (int h = 0; h < 8; ++h) {
            float pw = (p < 4) ? __shfl_sync(0xffffffffu, pA, p * 8 + h)
                               : __shfl_sync(0xffffffffu, pB, (p - 4) * 8 + h);
            acc[h].x = fmaf(pw, v4.x, acc[h].x);
            acc[h].y = fmaf(pw, v4.y, acc[h].y);
            acc[h].z = fmaf(pw, v4.z, acc[h].z);
            acc[h].w = fmaf(pw, v4.w, acc[h].w);
        }
    }
    __syncthreads();

    #pragma unroll
    for (int h = 0; h < 8; ++h)
        *(float4*)&sK[(w * 8 + h) * 128 + lane * 4] = acc[h];
    __syncthreads();

    {
        float4 r = make_float4(0.f, 0.f, 0.f, 0.f);
        #pragma unroll
        for (int ww = 0; ww < 8; ++ww) {
            float4 v = *(const float4*)&sK[(ww * 8 + w) * 128 + lane * 4];
            r.x += v.x; r.y += v.y; r.z += v.z; r.w += v.w;
        }
        float* pp = g_part + ((size_t)bidx * 8 + w) * 132;
        *(float4*)(pp + lane * 4) = r;
    }
}

// ---------------- combine partials -> bf16 hi/lo attn output ----------------
__global__ __launch_bounds__(256)
void combine_attn() {
    int w = blockIdx.x * 8 + (threadIdx.x >> 5);   // 0..2047 = (b,h)
    int lane = threadIdx.x & 31;
    int b = w >> 6, h = w & 63;
    int kv = h >> 3, r = h & 7;

    float m[8], s[8];
    float4 a[8];
    #pragma unroll
    for (int i = 0; i < 8; ++i) {
        const float* p = g_part + ((size_t)((b * 8 + kv) * 8 + i) * 8 + r) * 132;
        a[i] = *(const float4*)(p + lane * 4);
        m[i] = p[128];
        s[i] = p[129];
    }
    float M = m[0];
    #pragma unroll
    for (int i = 1; i < 8; ++i) M = fmaxf(M, m[i]);
    float wsum = 0.0f;
    float4 o = make_float4(0.f, 0.f, 0.f, 0.f);
    #pragma unroll
    for (int i = 0; i < 8; ++i) {
        float wi = __expf(m[i] - M);
        wsum += wi * s[i];
        o.x = fmaf(wi, a[i].x, o.x);
        o.y = fmaf(wi, a[i].y, o.y);
        o.z = fmaf(wi, a[i].z, o.z);
        o.w = fmaf(wi, a[i].w, o.w);
    }
    float inv = 1.0f / wsum;
    o.x *= inv; o.y *= inv; o.z *= inv; o.w *= inv;

    unsigned h0, l0, h1, l1;
    split2(o.x, o.y, h0, l0);
    split2(o.z, o.w, h1, l1);
    size_t wb = (size_t)b * 4096 + h * 64 + lane * 2;
    g_ahi[wb]     = h0;
    g_ahi[wb + 1] = h1;
    g_alo[wb]     = l0;
    g_alo[wb + 1] = l1;
}

// ---------------- launcher ----------------
extern "C" void kernel_launch(void* const* d_in, const int* in_sizes, int n_in,
                              void* d_out, int out_size) {
    const float* x  = (const float*)d_in[0];
    const float* wq = (const float*)d_in[1];
    const float* wk = (const float*)d_in[2];
    const float* wv = (const float*)d_in[3];
    const float* wo = (const float*)d_in[4];
    const float* ck = (const float*)d_in[5];
    const float* cv = (const float*)d_in[6];
    const float* rm = (const float*)d_in[7];
    float* out = (float*)d_out;

    cudaFuncSetAttribute(gemm_mma, cudaFuncAttributeMaxDynamicSharedMemorySize, SM_TOT);

    // 1. fused: zero g_qkv + d_out, split x into bf16 hi/lo
    prep_kernel<<<2816, 256>>>(x, out);

    // 2. fused QKV projection: 160 row-tiles x split-K 4, lookahead-2
    gemm_mma<<<dim3(160, 4), 256, SM_TOT>>>(0, wq, wk, wv, 8192, 9216,
                                            0, nullptr, NTOT);

    // 3. attention with fused RoPE: 8-way flash-decode split + combine
    attn_split<<<2048, 256>>>(ck, cv, rm);
    combine_attn<<<256, 256>>>();

    // 4. output projection: 128 row-tiles x split-K 4 into d_out
    gemm_mma<<<dim3(128, 4), 256, SM_TOT>>>(1, wo, wo, wo, 1 << 30, 1 << 30,
                                            1, out, HID_);
}

// round 17
// speedup vs baseline: 1.3460x; 1.3460x over previous
#include <cuda_runtime.h>
#include <cuda_bf16.h>

#define B_    32
#define H_    64
#define KVH_  8
#define D_    128
#define HID_  8192
#define CL_   1024
#define SP_   511
#define NTOT  10240

// ---------------- scratch ----------------
__device__ float    g_qkv[B_ * NTOT];
__device__ unsigned g_xhi[B_ * 4096];
__device__ unsigned g_xlo[B_ * 4096];
__device__ unsigned g_ahi[B_ * 4096];
__device__ unsigned g_alo[B_ * 4096];
__device__ float    g_part[2048 * 8 * 132];

// gemm smem (48 KB)
#define SMW_HI(buf) ((buf) * 8192)
#define SMW_LO(buf) (16384 + (buf) * 8192)
#define SMB_HI(buf) (32768 + (buf) * 4096)
#define SMB_LO(buf) (40960 + (buf) * 4096)
#define SM_TOT 49152

// ---------------- helpers ----------------
__device__ __forceinline__ void split2(float f0, float f1, unsigned& hi, unsigned& lo) {
    unsigned u0 = __float_as_uint(f0), u1 = __float_as_uint(f1);
    unsigned h;
    asm("prmt.b32 %0, %1, %2, 0x7632;" : "=r"(h) : "r"(u0), "r"(u1));
    float l0 = f0 - __uint_as_float(u0 & 0xffff0000u);
    float l1 = f1 - __uint_as_float(u1 & 0xffff0000u);
    unsigned v0 = __float_as_uint(l0), v1 = __float_as_uint(l1);
    unsigned l;
    asm("prmt.b32 %0, %1, %2, 0x7632;" : "=r"(l) : "r"(v0), "r"(v1));
    hi = h;
    lo = l;
}

__device__ __forceinline__ void ldsm4(unsigned& r0, unsigned& r1, unsigned& r2,
                                      unsigned& r3, unsigned addr) {
    asm volatile("ldmatrix.sync.aligned.m8n8.x4.shared.b16 {%0,%1,%2,%3}, [%4];"
                 : "=r"(r0), "=r"(r1), "=r"(r2), "=r"(r3) : "r"(addr));
}

__device__ __forceinline__ void mma16816(float* c, const unsigned* a,
                                         unsigned b0, unsigned b1) {
    asm volatile(
        "mma.sync.aligned.m16n8k16.row.col.f32.bf16.bf16.f32 "
        "{%0,%1,%2,%3}, {%4,%5,%6,%7}, {%8,%9}, {%0,%1,%2,%3};"
        : "+f"(c[0]), "+f"(c[1]), "+f"(c[2]), "+f"(c[3])
        : "r"(a[0]), "r"(a[1]), "r"(a[2]), "r"(a[3]), "r"(b0), "r"(b1));
}

__device__ __forceinline__ float4 rope4(float4 v, int l, const float* __restrict__ rm) {
    float c0 = rm[(4 * l)     * D_ + 4 * l];
    float s0 = rm[(4 * l + 1) * D_ + 4 * l];
    float c1 = rm[(4 * l + 2) * D_ + 4 * l + 2];
    float s1 = rm[(4 * l + 3) * D_ + 4 * l + 2];
    float4 r;
    r.x = fmaf(v.x, c0,  v.y * s0);
    r.y = fmaf(v.y, c0, -v.x * s0);
    r.z = fmaf(v.z, c1,  v.w * s1);
    r.w = fmaf(v.w, c1, -v.z * s1);
    return r;
}

// ---------------- fused zero + cvt ----------------
__global__ void prep_kernel(const float* __restrict__ x, float* __restrict__ out) {
    const int n1 = B_ * NTOT;
    const int n2 = B_ * HID_;
    const int n3 = B_ * HID_ / 2;
    int t = blockIdx.x * blockDim.x + threadIdx.x;
    if (t < n1) {
        g_qkv[t] = 0.0f;
    } else if (t < n1 + n2) {
        out[t - n1] = 0.0f;
    } else if (t < n1 + n2 + n3) {
        int i = t - n1 - n2;
        float f0 = x[2 * i], f1 = x[2 * i + 1];
        unsigned h, l;
        split2(f0, f1, h, l);
        g_xhi[i] = h;
        g_xlo[i] = l;
    }
}

// ---------------- HMMA GEMM (R15 winner config, byte-exact) -----------------
__global__ __launch_bounds__(256, 4)
void gemm_mma(int bsel,
              const float* __restrict__ W0, const float* __restrict__ W1,
              const float* __restrict__ W2,
              int nb1, int nb2,
              int csel, float* __restrict__ Cext, int ldc)
{
    extern __shared__ char smem[];
    unsigned sb = (unsigned)__cvta_generic_to_shared(smem);
    int tid = threadIdx.x, lane = tid & 31, wid = tid >> 5;

    int n0 = blockIdx.x * 64;
    const float* W; int wrow;
    if (n0 < nb1)      { W = W0; wrow = n0; }
    else if (n0 < nb2) { W = W1; wrow = n0 - nb1; }
    else               { W = W2; wrow = n0 - nb2; }

    const unsigned* __restrict__ Bh = bsel ? g_ahi : g_xhi;
    const unsigned* __restrict__ Bl = bsel ? g_alo : g_xlo;
    float* C = csel ? Cext : g_qkv;

    int kbase = blockIdx.y * (HID_ / 4);
    const float* wbase = W + (size_t)wrow * HID_ + kbase;
    int kw0 = kbase >> 1;

    int rg   = wid >> 1;
    int bh16 = wid & 1;

    int arow = rg * 16 + (lane & 7) + ((lane >> 3) & 1) * 8;
    int acs  = (lane >> 4) & 1;
    int arm  = arow & 7;
    int brow = bh16 * 16 + (lane & 7) + ((lane >> 4) & 1) * 8;
    int bcs  = (lane >> 3) & 1;
    int brm  = brow & 7;

    float4 wreg[4];
    uint4  bhreg, blreg;

    float acc[2][4];
    #pragma unroll
    for (int i = 0; i < 2; ++i)
        #pragma unroll
        for (int j = 0; j < 4; ++j) acc[i][j] = 0.0f;

    #define LOADC(c) do {                                                        \
        _Pragma("unroll")                                                        \
        for (int i_ = 0; i_ < 4; ++i_) {                                         \
            int idx_ = tid + 256 * i_;                                           \
            int row_ = idx_ >> 4, kq_ = idx_ & 15;                               \
            wreg[i_] = __ldcs((const float4*)(wbase + (c) * 64                   \
                              + (size_t)row_ * HID_ + kq_ * 4));                 \
        }                                                                        \
        {                                                                        \
            int n_ = tid >> 3, s_ = tid & 7;                                     \
            size_t off_ = (size_t)n_ * 4096 + kw0 + (c) * 32 + s_ * 4;           \
            bhreg = *(const uint4*)(Bh + off_);                                  \
            blreg = *(const uint4*)(Bl + off_);                                  \
        }                                                                        \
    } while (0)

    #define STOREC(buf) do {                                                     \
        _Pragma("unroll")                                                        \
        for (int i_ = 0; i_ < 4; ++i_) {                                         \
            int idx_ = tid + 256 * i_;                                           \
            int row_ = idx_ >> 4, kq_ = idx_ & 15;                               \
            unsigned h0_, l0_, h1_, l1_;                                         \
            split2(wreg[i_].x, wreg[i_].y, h0_, l0_);                            \
            split2(wreg[i_].z, wreg[i_].w, h1_, l1_);                            \
            unsigned off_ = (unsigned)(row_ * 128)                               \
                          + ((((unsigned)kq_ >> 1) ^ (unsigned)(row_ & 7)) << 4) \
                          + (((unsigned)kq_ & 1u) << 3);                         \
            *(uint2*)(smem + SMW_HI(buf) + off_) = make_uint2(h0_, h1_);         \
            *(uint2*)(smem + SMW_LO(buf) + off_) = make_uint2(l0_, l1_);         \
        }                                                                        \
        {                                                                        \
            int n_ = tid >> 3, s_ = tid & 7;                                     \
            unsigned off_ = (unsigned)(n_ * 128)                                 \
                          + (((unsigned)s_ ^ (unsigned)(n_ & 7)) << 4);          \
            *(uint4*)(smem + SMB_HI(buf) + off_) = bhreg;                        \
            *(uint4*)(smem + SMB_LO(buf) + off_) = blreg;                        \
        }                                                                        \
    } while (0)

    LOADC(0);
    STOREC(0);
    __syncthreads();

    const int NCH = (HID_ / 4) / 64;
    for (int c = 0; c < NCH; ++c) {
        int buf = c & 1;
        if (c + 1 < NCH) LOADC(c + 1);

        unsigned wh0 = sb + SMW_HI(buf), wl0 = sb + SMW_LO(buf);
        unsigned bb0 = sb + SMB_HI(buf), bl0 = sb + SMB_LO(buf);
        #pragma unroll
        for (int s = 0; s < 4; ++s) {
            unsigned aoff = (unsigned)(arow * 128)
                          + (((unsigned)(2 * s + acs) ^ (unsigned)arm) << 4);
            unsigned ah[4], al[4];
            ldsm4(ah[0], ah[1], ah[2], ah[3], wh0 + aoff);
            ldsm4(al[0], al[1], al[2], al[3], wl0 + aoff);
            unsigned boff = (unsigned)(brow * 128)
                          + (((unsigned)(2 * s + bcs) ^ (unsigned)brm) << 4);
            unsigned bh[4], bl[4];
            ldsm4(bh[0], bh[1], bh[2], bh[3], bb0 + boff);
            ldsm4(bl[0], bl[1], bl[2], bl[3], bl0 + boff);

            mma16816(acc[0], ah, bh[0], bh[1]);
            mma16816(acc[1], ah, bh[2], bh[3]);
            mma16816(acc[0], al, bh[0], bh[1]);
            mma16816(acc[1], al, bh[2], bh[3]);
            mma16816(acc[0], ah, bl[0], bl[1]);
            mma16816(acc[1], ah, bl[2], bl[3]);
        }

        if (c + 1 < NCH) STOREC((c + 1) & 1);
        __syncthreads();
    }

    int g = lane >> 2, t4 = lane & 3;
    int m = n0 + rg * 16 + g;
    #pragma unroll
    for (int nt = 0; nt < 2; ++nt) {
        int col = bh16 * 16 + nt * 8 + 2 * t4;
        atomicAdd(&C[(size_t)col * ldc + m],           acc[nt][0]);
        atomicAdd(&C[(size_t)(col + 1) * ldc + m],     acc[nt][1]);
        atomicAdd(&C[(size_t)col * ldc + m + 8],       acc[nt][2]);
        atomicAdd(&C[(size_t)(col + 1) * ldc + m + 8], acc[nt][3]);
    }
    #undef LOADC
    #undef STOREC
}

// ---------------- attention split v5: V direct from gmem (no V staging) -----
// Warp w owns positions w*8..w*8+7; each V row is consumed by exactly one
// warp, so V skips smem entirely: 8 coalesced LDG.128 into registers,
// issued before phase 1 (full-phase latency window). Crossbar/block -31%.
__global__ __launch_bounds__(256, 3)
void attn_split(const float* __restrict__ cache_k,
                const float* __restrict__ cache_v,
                const float* __restrict__ rm)
{
    __shared__ float sQ[8][128];
    __shared__ float sK[64 * 128];   // K tile, then output partials
    __shared__ float sS[64 * 9];

    int bidx  = blockIdx.x;
    int split = bidx & 7;
    int bk    = bidx >> 3;
    int b  = bk >> 3;
    int kv = bk & 7;
    int p0 = split * 64;

    int tid  = threadIdx.x;
    int w    = tid >> 5;
    int lane = tid & 31;

    const float scale = 0.0883883476483184405501055452631f;

    const float* kb   = cache_k + ((size_t)(b * KVH_ + kv)) * CL_ * D_;
    const float* vb   = cache_v + ((size_t)(b * KVH_ + kv)) * CL_ * D_;
    const float* knew = g_qkv + (size_t)b * NTOT + HID_ + kv * D_;
    const float* vnew = g_qkv + (size_t)b * NTOT + HID_ + KVH_ * D_ + kv * D_;

    // stage q (warp w -> head w; RoPE + scale fused)
    {
        float4 q = *(const float4*)(g_qkv + (size_t)b * NTOT + (kv * 8 + w) * D_ + lane * 4);
        q = rope4(q, lane, rm);
        q.x *= scale; q.y *= scale; q.z *= scale; q.w *= scale;
        *(float4*)&sQ[w][lane * 4] = q;
    }
    // stage K rows straight
    #pragma unroll
    for (int i = 0; i < 8; ++i) {
        int v = tid + 256 * i;
        int j = v >> 5, dq = v & 31;
        int s = p0 + j;
        float4 kd;
        if (s == SP_) kd = rope4(*(const float4*)(knew + dq * 4), dq, rm);
        else          kd = __ldcs((const float4*)(kb + (size_t)s * D_ + dq * 4));
        *(float4*)&sK[j * 128 + dq * 4] = kd;
    }
    __syncthreads();

    // V prefetch: warp's 8 rows, lane = chunk (coalesced; long latency window)
    float4 vreg[8];
    #pragma unroll
    for (int p = 0; p < 8; ++p) {
        int s = p0 + w * 8 + p;
        vreg[p] = (s == SP_) ? *(const float4*)(vnew + lane * 4)
                             : __ldcs((const float4*)(vb + (size_t)s * D_ + lane * 4));
    }

    // q into registers
    float4 qreg[8];
    #pragma unroll
    for (int h = 0; h < 8; ++h)
        qreg[h] = *(const float4*)&sQ[h][lane * 4];

    // ---- phase 1: scores for warp's 8 rows x 8 heads ----
    #pragma unroll
    for (int p = 0; p < 8; ++p) {
        int j = w * 8 + p;
        float4 v4 = *(const float4*)&sK[j * 128 + lane * 4];
        float pr[8];
        #pragma unroll
        for (int h = 0; h < 8; ++h)
            pr[h] = fmaf(qreg[h].x, v4.x, fmaf(qreg[h].y, v4.y,
                    fmaf(qreg[h].z, v4.z, qreg[h].w * v4.w)));
        #pragma unroll
        for (int h = 0; h < 8; ++h) {
            pr[h] += __shfl_xor_sync(0xffffffffu, pr[h], 16);
            pr[h] += __shfl_xor_sync(0xffffffffu, pr[h], 8);
        }
        float s4[4];
        #pragma unroll
        for (int i = 0; i < 4; ++i) {
            float r1 = __shfl_xor_sync(0xffffffffu, pr[i], 4);
            float r2 = __shfl_xor_sync(0xffffffffu, pr[i + 4], 4);
            s4[i] = (lane & 4) ? (pr[i + 4] + r2) : (pr[i] + r1);
        }
        float s2[2];
        #pragma unroll
        for (int i = 0; i < 2; ++i) {
            float r1 = __shfl_xor_sync(0xffffffffu, s4[i], 2);
            float r2 = __shfl_xor_sync(0xffffffffu, s4[i + 2], 2);
            s2[i] = (lane & 2) ? (s4[i + 2] + r2) : (s4[i] + r1);
        }
        float r1 = __shfl_xor_sync(0xffffffffu, s2[0], 1);
        float r2 = __shfl_xor_sync(0xffffffffu, s2[1], 1);
        float f  = (lane & 1) ? (s2[1] + r2) : (s2[0] + r1);
        if (lane < 8) sS[j * 9 + lane] = f;
    }
    __syncthreads();

    // ---- phase 2: softmax (warp w = head w) ----
    {
        float v1 = sS[lane * 9 + w];
        float v2 = sS[(lane + 32) * 9 + w];
        float mx = fmaxf(v1, v2);
        #pragma unroll
        for (int o = 16; o; o >>= 1) mx = fmaxf(mx, __shfl_xor_sync(0xffffffffu, mx, o));
        float e1 = __expf(v1 - mx), e2 = __expf(v2 - mx);
        float sum = e1 + e2;
        #pragma unroll
        for (int o = 16; o; o >>= 1) sum += __shfl_xor_sync(0xffffffffu, sum, o);
        sS[lane * 9 + w]        = e1;
        sS[(lane + 32) * 9 + w] = e2;
        if (lane == 0) {
            float* pp = g_part + ((size_t)bidx * 8 + w) * 132;
            pp[128] = mx;
            pp[129] = sum;
        }
    }
    __syncthreads();

    // ---- phase 3: partial output from vreg (no smem V) ----
    float pA = sS[(w * 8 +     (lane >> 3)) * 9 + (lane & 7)];
    float pB = sS[(w * 8 + 4 + (lane >> 3)) * 9 + (lane & 7)];
    float4 acc[8];
    #pragma unroll
    for (int h = 0; h < 8; ++h) acc[h] = make_float4(0.f, 0.f, 0.f, 0.f);
    #pragma unroll
    for (int p = 0; p < 8; ++p) {
        float4 v4 = vreg[p];
        #pragma unroll
        for (int h = 0; h < 8; ++h) {
            float pw = (p < 4) ? __shfl_sync(0xffffffffu, pA, p * 8 + h)
                               : __shfl_sync(0xffffffffu, pB, (p - 4) * 8 + h);
            acc[h].x = fmaf(pw, v4.x, acc[h].x);
            acc[h].y = fmaf(pw, v4.y, acc[h].y);
            acc[h].z = fmaf(pw, v4.z, acc[h].z);
            acc[h].w = fmaf(pw, v4.w, acc[h].w);
        }
    }

    // write per-warp partials into sK (safe: sK last read before phase-1 sync)
    #pragma unroll
    for (int h = 0; h < 8; ++h)
        *(float4*)&sK[(w * 8 + h) * 128 + lane * 4] = acc[h];
    __syncthreads();

    // final reduce: warp w = head w, lane = chunk
    {
        float4 r = make_float4(0.f, 0.f, 0.f, 0.f);
        #pragma unroll
        for (int ww = 0; ww < 8; ++ww) {
            float4 v = *(const float4*)&sK[(ww * 8 + w) * 128 + lane * 4];
            r.x += v.x; r.y += v.y; r.z += v.z; r.w += v.w;
        }
        float* pp = g_part + ((size_t)bidx * 8 + w) * 132;
        *(float4*)(pp + lane * 4) = r;
    }
}

// ---------------- combine partials -> bf16 hi/lo attn output ----------------
__global__ __launch_bounds__(256)
void combine_attn() {
    int w = blockIdx.x * 8 + (threadIdx.x >> 5);
    int lane = threadIdx.x & 31;
    int b = w >> 6, h = w & 63;
    int kv = h >> 3, r = h & 7;

    float m[8], s[8];
    float4 a[8];
    #pragma unroll
    for (int i = 0; i < 8; ++i) {
        const float* p = g_part + ((size_t)((b * 8 + kv) * 8 + i) * 8 + r) * 132;
        a[i] = *(const float4*)(p + lane * 4);
        m[i] = p[128];
        s[i] = p[129];
    }
    float M = m[0];
    #pragma unroll
    for (int i = 1; i < 8; ++i) M = fmaxf(M, m[i]);
    float wsum = 0.0f;
    float4 o = make_float4(0.f, 0.f, 0.f, 0.f);
    #pragma unroll
    for (int i = 0; i < 8; ++i) {
        float wi = __expf(m[i] - M);
        wsum += wi * s[i];
        o.x = fmaf(wi, a[i].x, o.x);
        o.y = fmaf(wi, a[i].y, o.y);
        o.z = fmaf(wi, a[i].z, o.z);
        o.w = fmaf(wi, a[i].w, o.w);
    }
    float inv = 1.0f / wsum;
    o.x *= inv; o.y *= inv; o.z *= inv; o.w *= inv;

    unsigned h0, l0, h1, l1;
    split2(o.x, o.y, h0, l0);
    split2(o.z, o.w, h1, l1);
    size_t wb = (size_t)b * 4096 + h * 64 + lane * 2;
    g_ahi[wb]     = h0;
    g_ahi[wb + 1] = h1;
    g_alo[wb]     = l0;
    g_alo[wb + 1] = l1;
}

// ---------------- launcher ----------------
extern "C" void kernel_launch(void* const* d_in, const int* in_sizes, int n_in,
                              void* d_out, int out_size) {
    const float* x  = (const float*)d_in[0];
    const float* wq = (const float*)d_in[1];
    const float* wk = (const float*)d_in[2];
    const float* wv = (const float*)d_in[3];
    const float* wo = (const float*)d_in[4];
    const float* ck = (const float*)d_in[5];
    const float* cv = (const float*)d_in[6];
    const float* rm = (const float*)d_in[7];
    float* out = (float*)d_out;

    cudaFuncSetAttribute(gemm_mma, cudaFuncAttributeMaxDynamicSharedMemorySize, SM_TOT);

    // 1. fused: zero g_qkv + d_out, split x into bf16 hi/lo
    prep_kernel<<<2816, 256>>>(x, out);

    // 2. fused QKV projection: 160 row-tiles x split-K 4 (R15 winner config)
    gemm_mma<<<dim3(160, 4), 256, SM_TOT>>>(0, wq, wk, wv, 8192, 9216,
                                            0, nullptr, NTOT);

    // 3. attention with fused RoPE: 8-way split, V direct from gmem + combine
    attn_split<<<2048, 256>>>(ck, cv, rm);
    combine_attn<<<256, 256>>>();

    // 4. output projection: 128 row-tiles x split-K 4 into d_out
    gemm_mma<<<dim3(128, 4), 256, SM_TOT>>>(1, wo, wo, wo, 1 << 30, 1 << 30,
                                            1, out, HID_);
}